// round 1
// baseline (speedup 1.0000x reference)
#include <cuda_runtime.h>
#include <cstdint>

#define B_ 4
#define S_ 1024
#define E_ 1024
#define H_ 16
#define D_ 64

// scratch (device globals; no allocation allowed)
__device__ float g_q[B_*S_*E_];
__device__ float g_k[B_*S_*E_];
__device__ float g_v[B_*S_*E_];
__device__ float g_ctx[B_*S_*E_];
__device__ float g_g[B_*E_];
__device__ float g_gq[B_*E_];
__device__ float g_gk[B_*E_];
__device__ float g_minv[B_];

// ---------------------------------------------------------------------------
// mask row sums -> 1/clip(sum)
__global__ void msum_kernel(const int* __restrict__ mask) {
    int b = threadIdx.x >> 5, lane = threadIdx.x & 31;
    float s = 0.f;
    for (int j = lane; j < S_; j += 32) s += (float)mask[b*S_ + j];
    #pragma unroll
    for (int o = 16; o; o >>= 1) s += __shfl_xor_sync(0xffffffffu, s, o);
    if (lane == 0) g_minv[b] = 1.0f / fmaxf(s, 1e-9f);
}

// masked mean over sequence: g[b,e] = sum_s x[s,b,e]*m / clip(sum m)
__global__ void mean_kernel(const float* __restrict__ x, const int* __restrict__ mask) {
    __shared__ float part[4][64];
    int b  = blockIdx.y;
    int e0 = blockIdx.x * 64;
    int el = threadIdx.x & 63, sq = threadIdx.x >> 6;
    float acc = 0.f;
    int sbeg = sq * 256;
    for (int s = sbeg; s < sbeg + 256; s++) {
        float m = (float)mask[b*S_ + s];
        acc += x[((size_t)s*B_ + b)*E_ + e0 + el] * m;
    }
    part[sq][el] = acc;
    __syncthreads();
    if (threadIdx.x < 64) {
        float t = part[0][el] + part[1][el] + part[2][el] + part[3][el];
        g_g[b*E_ + e0 + el] = t * g_minv[b];
    }
}

// ---------------------------------------------------------------------------
// Y[t, n] = sum_k A[t, k] * W[n, k] + bias[n]
// M=4096 (t = b*S + s), N=K=1024.
// permIn : A memory row = s*B + b   (x is (S,B,E))
// permOut: Y memory row = s*B + b   (final output is (S,B,E))
__global__ void __launch_bounds__(256) sgemm128(
    const float* __restrict__ A, const float* __restrict__ W,
    const float* __restrict__ bias, float* __restrict__ Y,
    int permIn, int permOut)
{
    __shared__ float As[8][132];
    __shared__ float Bs[8][132];
    const int K = 1024, N = 1024;
    int tid = threadIdx.x;
    int tx = tid & 15, ty = tid >> 4;
    int lrow = tid >> 1, lk = (tid & 1) * 4;

    int am   = blockIdx.y * 128 + lrow;
    int arow = permIn ? ((am & 1023) * B_ + (am >> 10)) : am;
    int bn   = blockIdx.x * 128 + lrow;
    const float* Aptr = A + (size_t)arow * K + lk;
    const float* Wptr = W + (size_t)bn   * K + lk;

    float acc[8][8];
    #pragma unroll
    for (int i = 0; i < 8; i++)
        #pragma unroll
        for (int j = 0; j < 8; j++) acc[i][j] = 0.f;

    for (int k0 = 0; k0 < K; k0 += 8) {
        float4 av = *(const float4*)(Aptr + k0);
        float4 bv = *(const float4*)(Wptr + k0);
        As[lk+0][lrow] = av.x; As[lk+1][lrow] = av.y;
        As[lk+2][lrow] = av.z; As[lk+3][lrow] = av.w;
        Bs[lk+0][lrow] = bv.x; Bs[lk+1][lrow] = bv.y;
        Bs[lk+2][lrow] = bv.z; Bs[lk+3][lrow] = bv.w;
        __syncthreads();
        #pragma unroll
        for (int kk = 0; kk < 8; kk++) {
            float4 a0 = *(const float4*)&As[kk][ty*8];
            float4 a1 = *(const float4*)&As[kk][ty*8 + 4];
            float4 b0 = *(const float4*)&Bs[kk][tx*8];
            float4 b1 = *(const float4*)&Bs[kk][tx*8 + 4];
            float a[8] = {a0.x,a0.y,a0.z,a0.w,a1.x,a1.y,a1.z,a1.w};
            float bb[8] = {b0.x,b0.y,b0.z,b0.w,b1.x,b1.y,b1.z,b1.w};
            #pragma unroll
            for (int i = 0; i < 8; i++)
                #pragma unroll
                for (int j = 0; j < 8; j++)
                    acc[i][j] += a[i] * bb[j];
        }
        __syncthreads();
    }

    int ncol = blockIdx.x * 128 + tx * 8;
    #pragma unroll
    for (int i = 0; i < 8; i++) {
        int m = blockIdx.y * 128 + ty * 8 + i;
        int orow = permOut ? ((m & 1023) * B_ + (m >> 10)) : m;
        float* yrow = Y + (size_t)orow * N + ncol;
        #pragma unroll
        for (int j = 0; j < 8; j++) yrow[j] = acc[i][j] + bias[ncol + j];
    }
}

// ---------------------------------------------------------------------------
// gq[b,o] = sum_e g[b,e] * Wg[o,e] + bg[o]   (warp per output)
__global__ void gproj_kernel(const float* __restrict__ Wg, const float* __restrict__ bg,
                             float* __restrict__ out)
{
    int gw = (blockIdx.x * blockDim.x + threadIdx.x) >> 5;
    int lane = threadIdx.x & 31;
    int b = gw >> 10, o = gw & 1023;
    float acc = 0.f;
    #pragma unroll
    for (int e = lane * 4; e < E_; e += 128) {
        float4 gv = *(const float4*)&g_g[b*E_ + e];
        float4 wv = *(const float4*)&Wg[(size_t)o*E_ + e];
        acc += gv.x*wv.x + gv.y*wv.y + gv.z*wv.z + gv.w*wv.w;
    }
    #pragma unroll
    for (int of = 16; of; of >>= 1) acc += __shfl_xor_sync(0xffffffffu, acc, of);
    if (lane == 0) out[b*E_ + o] = acc + bg[o];
}

// ---------------------------------------------------------------------------
// gate: alpha = sigmoid(q.wv + bv + g.wg + bg); buf = (1-alpha)buf + alpha*g
// warp per (b,h,s) row; D=64 -> 2 elements per lane
__global__ void gate_kernel(float* __restrict__ buf, const float* __restrict__ gbuf,
                            const float* __restrict__ wv, const float* __restrict__ bvp,
                            const float* __restrict__ wg, const float* __restrict__ bgp)
{
    int gw   = (blockIdx.x * blockDim.x + threadIdx.x) >> 5;
    int lane = threadIdx.x & 31;
    int b = gw >> 14, h = (gw >> 10) & 15, s = gw & 1023;
    size_t off = ((size_t)(b*S_ + s))*E_ + h*D_;
    int goff = b*E_ + h*D_;
    float q0 = buf[off + lane],        q1 = buf[off + 32 + lane];
    float g0 = gbuf[goff + lane],      g1 = gbuf[goff + 32 + lane];
    float part = q0*wv[lane] + q1*wv[32 + lane] + g0*wg[lane] + g1*wg[32 + lane];
    #pragma unroll
    for (int o = 16; o; o >>= 1) part += __shfl_xor_sync(0xffffffffu, part, o);
    float alpha = 1.f / (1.f + __expf(-(part + bvp[0] + bgp[0])));
    buf[off + lane]      = q0 + alpha * (g0 - q0);
    buf[off + 32 + lane] = q1 + alpha * (g1 - q1);
}

// ---------------------------------------------------------------------------
// fused attention: per block = (b, h, 32-row q tile)
// phase1: scores (32 x 1024) in smem; phase2: softmax + write p_attn;
// phase3: out = p @ v -> ctx (B,S,E layout)
#define SC_FLOATS (32*1024)
#define QS_FLOATS (32*64)
#define KT_FLOATS (64*68)
#define MK_FLOATS (1024)
#define ATTN_SMEM_BYTES ((SC_FLOATS + QS_FLOATS + KT_FLOATS + MK_FLOATS) * 4)

__global__ void __launch_bounds__(256) attn_kernel(
    const float* __restrict__ q, const float* __restrict__ k,
    const float* __restrict__ v, const int* __restrict__ mask,
    float* __restrict__ p_out, float* __restrict__ ctx)
{
    extern __shared__ float sm[];
    float* sc = sm;                         // [32][1024] scores/probs
    float* qs = sm + SC_FLOATS;             // [32][64]
    float* kt = qs + QS_FLOATS;             // [64][68] k transposed (d,j); reused as v (j,d)
    float* mk = kt + KT_FLOATS;             // [1024] mask row

    int b = blockIdx.z, h = blockIdx.y, i0 = blockIdx.x * 32;
    int tid = threadIdx.x;

    for (int idx = tid; idx < 32*64; idx += 256) {
        int i = idx >> 6, d = idx & 63;
        qs[idx] = q[((size_t)(b*S_ + i0 + i))*E_ + h*D_ + d] * 0.125f; // 1/sqrt(64)
    }
    for (int j = tid; j < S_; j += 256) mk[j] = (float)mask[b*S_ + j];
    __syncthreads();

    int ti = tid >> 4, tj = tid & 15;

    // ---- phase 1: scores ----
    for (int jt = 0; jt < 16; jt++) {
        int j0 = jt * 64;
        #pragma unroll
        for (int t = 0; t < 4; t++) {
            int idx = tid + t * 256;
            int j = idx >> 4, d4 = (idx & 15) << 2;
            float4 kv = *(const float4*)&k[((size_t)(b*S_ + j0 + j))*E_ + h*D_ + d4];
            kt[(d4+0)*68 + j] = kv.x;
            kt[(d4+1)*68 + j] = kv.y;
            kt[(d4+2)*68 + j] = kv.z;
            kt[(d4+3)*68 + j] = kv.w;
        }
        __syncthreads();
        float acc0[4] = {0,0,0,0}, acc1[4] = {0,0,0,0};
        #pragma unroll 16
        for (int kk = 0; kk < 64; kk++) {
            float a0 = qs[ti*64 + kk];
            float a1 = qs[(ti+16)*64 + kk];
            float4 bv4 = *(const float4*)&kt[kk*68 + tj*4];
            acc0[0] += a0*bv4.x; acc0[1] += a0*bv4.y; acc0[2] += a0*bv4.z; acc0[3] += a0*bv4.w;
            acc1[0] += a1*bv4.x; acc1[1] += a1*bv4.y; acc1[2] += a1*bv4.z; acc1[3] += a1*bv4.w;
        }
        #pragma unroll
        for (int jj = 0; jj < 4; jj++) {
            sc[ti*1024 + j0 + tj*4 + jj]      = acc0[jj];
            sc[(ti+16)*1024 + j0 + tj*4 + jj] = acc1[jj];
        }
        __syncthreads();
    }

    // ---- phase 2: softmax + write p ----
    int wid = tid >> 5, lane = tid & 31;
    for (int r = wid; r < 32; r += 8) {
        float* row = sc + r * 1024;
        float mx = -1e30f;
        for (int j = lane; j < 1024; j += 32) {
            float sv = (mk[j] != 0.f) ? row[j] : -1e9f;
            row[j] = sv;
            mx = fmaxf(mx, sv);
        }
        #pragma unroll
        for (int o = 16; o; o >>= 1) mx = fmaxf(mx, __shfl_xor_sync(0xffffffffu, mx, o));
        float sum = 0.f;
        for (int j = lane; j < 1024; j += 32) {
            float e = __expf(row[j] - mx);
            row[j] = e;
            sum += e;
        }
        #pragma unroll
        for (int o = 16; o; o >>= 1) sum += __shfl_xor_sync(0xffffffffu, sum, o);
        float inv = 1.f / sum;
        float* prow = p_out + (((size_t)(b*H_ + h))*S_ + i0 + r) * S_;
        for (int j = lane; j < 1024; j += 32) {
            float pv = row[j] * inv;
            row[j] = pv;
            prow[j] = pv;
        }
    }
    __syncthreads();

    // ---- phase 3: out = p @ v ----
    float o0[4] = {0,0,0,0}, o1[4] = {0,0,0,0};
    float* vs = kt;  // reuse, layout [j][68]
    for (int jt = 0; jt < 16; jt++) {
        int j0 = jt * 64;
        #pragma unroll
        for (int t = 0; t < 4; t++) {
            int idx = tid + t * 256;
            int j = idx >> 4, d4 = (idx & 15) << 2;
            *(float4*)&vs[j*68 + d4] =
                *(const float4*)&v[((size_t)(b*S_ + j0 + j))*E_ + h*D_ + d4];
        }
        __syncthreads();
        #pragma unroll 16
        for (int j = 0; j < 64; j++) {
            float p0 = sc[ti*1024 + j0 + j];
            float p1 = sc[(ti+16)*1024 + j0 + j];
            float4 vv = *(const float4*)&vs[j*68 + tj*4];
            o0[0] += p0*vv.x; o0[1] += p0*vv.y; o0[2] += p0*vv.z; o0[3] += p0*vv.w;
            o1[0] += p1*vv.x; o1[1] += p1*vv.y; o1[2] += p1*vv.z; o1[3] += p1*vv.w;
        }
        __syncthreads();
    }
    size_t c0 = ((size_t)(b*S_ + i0 + ti))*E_ + h*D_ + tj*4;
    size_t c1 = ((size_t)(b*S_ + i0 + ti + 16))*E_ + h*D_ + tj*4;
    *(float4*)&ctx[c0] = make_float4(o0[0], o0[1], o0[2], o0[3]);
    *(float4*)&ctx[c1] = make_float4(o1[0], o1[1], o1[2], o1[3]);
}

// ---------------------------------------------------------------------------
extern "C" void kernel_launch(void* const* d_in, const int* in_sizes, int n_in,
                              void* d_out, int out_size)
{
    const float* x    = (const float*)d_in[0];
    const int*   mask = (const int*)  d_in[1];
    const float* Wq = (const float*)d_in[2];
    const float* bq = (const float*)d_in[3];
    const float* Wk = (const float*)d_in[4];
    const float* bk = (const float*)d_in[5];
    const float* Wv = (const float*)d_in[6];
    const float* bv = (const float*)d_in[7];
    const float* Wo = (const float*)d_in[8];
    const float* bo = (const float*)d_in[9];
    const float* Wgq = (const float*)d_in[10];
    const float* bgq = (const float*)d_in[11];
    const float* Wgk = (const float*)d_in[12];
    const float* bgk = (const float*)d_in[13];
    const float* qg_wq = (const float*)d_in[14];
    const float* qg_bq = (const float*)d_in[15];
    const float* qg_wk = (const float*)d_in[16];
    const float* qg_bk = (const float*)d_in[17];
    const float* kg_wq = (const float*)d_in[18];
    const float* kg_bq = (const float*)d_in[19];
    const float* kg_wk = (const float*)d_in[20];
    const float* kg_bk = (const float*)d_in[21];

    float* out   = (float*)d_out;
    float* p_out = out + (size_t)S_ * B_ * E_;

    float *qb, *kb, *vb, *ctxb, *gqb, *gkb;
    cudaGetSymbolAddress((void**)&qb,   g_q);
    cudaGetSymbolAddress((void**)&kb,   g_k);
    cudaGetSymbolAddress((void**)&vb,   g_v);
    cudaGetSymbolAddress((void**)&ctxb, g_ctx);
    cudaGetSymbolAddress((void**)&gqb,  g_gq);
    cudaGetSymbolAddress((void**)&gkb,  g_gk);

    cudaFuncSetAttribute(attn_kernel, cudaFuncAttributeMaxDynamicSharedMemorySize,
                         ATTN_SMEM_BYTES);

    msum_kernel<<<1, 128>>>(mask);
    mean_kernel<<<dim3(E_/64, B_), 256>>>(x, mask);

    sgemm128<<<dim3(8, 32), 256>>>(x, Wq, bq, qb, 1, 0);
    sgemm128<<<dim3(8, 32), 256>>>(x, Wk, bk, kb, 1, 0);
    sgemm128<<<dim3(8, 32), 256>>>(x, Wv, bv, vb, 1, 0);

    gproj_kernel<<<512, 256>>>(Wgq, bgq, gqb);
    gproj_kernel<<<512, 256>>>(Wgk, bgk, gkb);

    gate_kernel<<<8192, 256>>>(qb, gqb, qg_wq, qg_bq, qg_wk, qg_bk);
    gate_kernel<<<8192, 256>>>(kb, gkb, kg_wq, kg_bq, kg_wk, kg_bk);

    attn_kernel<<<dim3(S_/32, H_, B_), 256, ATTN_SMEM_BYTES>>>(
        qb, kb, vb, mask, p_out, ctxb);

    sgemm128<<<dim3(8, 32), 256>>>(ctxb, Wo, bo, out, 0, 1);
}

// round 2
// speedup vs baseline: 2.0568x; 2.0568x over previous
#include <cuda_runtime.h>
#include <cstdint>

#define B_ 4
#define S_ 1024
#define E_ 1024
#define H_ 16
#define D_ 64

__device__ float g_q[B_*S_*E_];
__device__ float g_k[B_*S_*E_];
__device__ float g_v[B_*S_*E_];
__device__ float g_ctx[B_*S_*E_];
__device__ float g_g[B_*E_];
__device__ float g_gq[B_*E_];
__device__ float g_gk[B_*E_];
__device__ float g_minv[B_];

__device__ __forceinline__ uint32_t f2tf(float f) {
    uint32_t u;
    asm("cvt.rna.tf32.f32 %0, %1;" : "=r"(u) : "f"(f));
    return u;
}

__device__ __forceinline__ void mma_tf32(float c[4],
    uint32_t a0, uint32_t a1, uint32_t a2, uint32_t a3,
    uint32_t b0, uint32_t b1)
{
    asm volatile(
        "mma.sync.aligned.m16n8k8.row.col.f32.tf32.tf32.f32 "
        "{%0,%1,%2,%3}, {%4,%5,%6,%7}, {%8,%9}, {%0,%1,%2,%3};"
        : "+f"(c[0]), "+f"(c[1]), "+f"(c[2]), "+f"(c[3])
        : "r"(a0), "r"(a1), "r"(a2), "r"(a3), "r"(b0), "r"(b1));
}

__device__ __forceinline__ void cp16(uint32_t saddr, const void* g) {
    asm volatile("cp.async.cg.shared.global [%0], [%1], 16;" :: "r"(saddr), "l"(g));
}

// ---------------------------------------------------------------------------
__global__ void msum_kernel(const int* __restrict__ mask) {
    int b = threadIdx.x >> 5, lane = threadIdx.x & 31;
    float s = 0.f;
    for (int j = lane; j < S_; j += 32) s += (float)mask[b*S_ + j];
    #pragma unroll
    for (int o = 16; o; o >>= 1) s += __shfl_xor_sync(0xffffffffu, s, o);
    if (lane == 0) g_minv[b] = 1.0f / fmaxf(s, 1e-9f);
}

__global__ void mean_kernel(const float* __restrict__ x, const int* __restrict__ mask) {
    __shared__ float part[4][64];
    int b  = blockIdx.y;
    int e0 = blockIdx.x * 64;
    int el = threadIdx.x & 63, sq = threadIdx.x >> 6;
    float acc = 0.f;
    int sbeg = sq * 256;
    for (int s = sbeg; s < sbeg + 256; s++) {
        float m = (float)mask[b*S_ + s];
        acc += x[((size_t)s*B_ + b)*E_ + e0 + el] * m;
    }
    part[sq][el] = acc;
    __syncthreads();
    if (threadIdx.x < 64) {
        float t = part[0][el] + part[1][el] + part[2][el] + part[3][el];
        g_g[b*E_ + e0 + el] = t * g_minv[b];
    }
}

// ---------------------------------------------------------------------------
// tf32 tensor-core GEMM: Y[t,n] = sum_k A[t,k] * W[n,k] + bias[n]
#define GPAD 20
#define GSTG (128*GPAD)

__global__ void __launch_bounds__(256) tgemm(
    const float* __restrict__ A, const float* __restrict__ W,
    const float* __restrict__ bias, float* __restrict__ Y,
    int permIn, int permOut)
{
    __shared__ float As[2][GSTG];
    __shared__ float Bs[2][GSTG];
    const int tid = threadIdx.x;
    const int lane = tid & 31, warp = tid >> 5;
    const int wm = (warp & 1) * 64, wn = (warp >> 1) * 32;
    const int r4 = lane >> 2, c4 = lane & 3;

    uint32_t aBase = (uint32_t)__cvta_generic_to_shared(&As[0][0]);
    uint32_t bBase = (uint32_t)__cvta_generic_to_shared(&Bs[0][0]);

    int row0 = tid >> 2,         k40 = (tid & 3) * 4;
    int row1 = (tid + 256) >> 2, k41 = ((tid + 256) & 3) * 4;
    int am0 = blockIdx.y*128 + row0;
    int am1 = blockIdx.y*128 + row1;
    int ar0 = permIn ? ((am0 & 1023)*B_ + (am0 >> 10)) : am0;
    int ar1 = permIn ? ((am1 & 1023)*B_ + (am1 >> 10)) : am1;
    const float* ap0 = A + (size_t)ar0*1024 + k40;
    const float* ap1 = A + (size_t)ar1*1024 + k41;
    const float* wp0 = W + ((size_t)(blockIdx.x*128 + row0))*1024 + k40;
    const float* wp1 = W + ((size_t)(blockIdx.x*128 + row1))*1024 + k41;
    uint32_t ad0 = aBase + (row0*GPAD + k40)*4, ad1 = aBase + (row1*GPAD + k41)*4;
    uint32_t bd0 = bBase + (row0*GPAD + k40)*4, bd1 = bBase + (row1*GPAD + k41)*4;

    auto loadStage = [&](int stg, int k0) {
        uint32_t so = stg * GSTG * 4;
        cp16(ad0 + so, ap0 + k0);
        cp16(ad1 + so, ap1 + k0);
        cp16(bd0 + so, wp0 + k0);
        cp16(bd1 + so, wp1 + k0);
        asm volatile("cp.async.commit_group;" ::: "memory");
    };

    float acc[4][4][4];
    #pragma unroll
    for (int mi = 0; mi < 4; mi++)
        #pragma unroll
        for (int nj = 0; nj < 4; nj++)
            #pragma unroll
            for (int t = 0; t < 4; t++) acc[mi][nj][t] = 0.f;

    loadStage(0, 0);
    for (int ks = 0; ks < 64; ks++) {
        if (ks < 63) {
            loadStage((ks + 1) & 1, (ks + 1) * 16);
            asm volatile("cp.async.wait_group 1;" ::: "memory");
        } else {
            asm volatile("cp.async.wait_group 0;" ::: "memory");
        }
        __syncthreads();
        const float* as = As[ks & 1];
        const float* bs = Bs[ks & 1];
        #pragma unroll
        for (int kk = 0; kk < 16; kk += 8) {
            uint32_t af[4][4];
            #pragma unroll
            for (int mi = 0; mi < 4; mi++) {
                const float* ap = as + (wm + mi*16 + r4)*GPAD + kk + c4;
                af[mi][0] = f2tf(ap[0]);
                af[mi][1] = f2tf(ap[8*GPAD]);
                af[mi][2] = f2tf(ap[4]);
                af[mi][3] = f2tf(ap[8*GPAD + 4]);
            }
            #pragma unroll
            for (int nj = 0; nj < 4; nj++) {
                const float* bp = bs + (wn + nj*8 + r4)*GPAD + kk + c4;
                uint32_t b0 = f2tf(bp[0]), b1 = f2tf(bp[4]);
                #pragma unroll
                for (int mi = 0; mi < 4; mi++)
                    mma_tf32(acc[mi][nj], af[mi][0], af[mi][1], af[mi][2], af[mi][3], b0, b1);
            }
        }
        __syncthreads();
    }

    #pragma unroll
    for (int mi = 0; mi < 4; mi++) {
        #pragma unroll
        for (int r2 = 0; r2 < 2; r2++) {
            int m = blockIdx.y*128 + wm + mi*16 + r4 + r2*8;
            int orow = permOut ? ((m & 1023)*B_ + (m >> 10)) : m;
            float* yp = Y + (size_t)orow*1024 + blockIdx.x*128 + wn;
            const float* bi = bias + blockIdx.x*128 + wn;
            #pragma unroll
            for (int nj = 0; nj < 4; nj++) {
                int c = nj*8 + 2*c4;
                float2 val;
                val.x = acc[mi][nj][r2*2 + 0] + bi[c];
                val.y = acc[mi][nj][r2*2 + 1] + bi[c + 1];
                *(float2*)(yp + c) = val;
            }
        }
    }
}

// ---------------------------------------------------------------------------
__global__ void gproj_kernel(const float* __restrict__ Wg, const float* __restrict__ bg,
                             float* __restrict__ out)
{
    int gw = (blockIdx.x * blockDim.x + threadIdx.x) >> 5;
    int lane = threadIdx.x & 31;
    int b = gw >> 10, o = gw & 1023;
    float acc = 0.f;
    #pragma unroll
    for (int e = lane * 4; e < E_; e += 128) {
        float4 gv = *(const float4*)&g_g[b*E_ + e];
        float4 wv = *(const float4*)&Wg[(size_t)o*E_ + e];
        acc += gv.x*wv.x + gv.y*wv.y + gv.z*wv.z + gv.w*wv.w;
    }
    #pragma unroll
    for (int of = 16; of; of >>= 1) acc += __shfl_xor_sync(0xffffffffu, acc, of);
    if (lane == 0) out[b*E_ + o] = acc + bg[o];
}

__global__ void gate_kernel(float* __restrict__ buf, const float* __restrict__ gbuf,
                            const float* __restrict__ wv, const float* __restrict__ bvp,
                            const float* __restrict__ wg, const float* __restrict__ bgp)
{
    int gw   = (blockIdx.x * blockDim.x + threadIdx.x) >> 5;
    int lane = threadIdx.x & 31;
    int b = gw >> 14, h = (gw >> 10) & 15, s = gw & 1023;
    size_t off = ((size_t)(b*S_ + s))*E_ + h*D_;
    int goff = b*E_ + h*D_;
    float q0 = buf[off + lane],        q1 = buf[off + 32 + lane];
    float g0 = gbuf[goff + lane],      g1 = gbuf[goff + 32 + lane];
    float part = q0*wv[lane] + q1*wv[32 + lane] + g0*wg[lane] + g1*wg[32 + lane];
    #pragma unroll
    for (int o = 16; o; o >>= 1) part += __shfl_xor_sync(0xffffffffu, part, o);
    float alpha = 1.f / (1.f + __expf(-(part + bvp[0] + bgp[0])));
    buf[off + lane]      = q0 + alpha * (g0 - q0);
    buf[off + 32 + lane] = q1 + alpha * (g1 - q1);
}

// ---------------------------------------------------------------------------
#define SCP 1028
#define ATTN_SMEM_FLOATS (32*SCP + 32*68 + 64*68 + 1024)
#define ATTN_SMEM_BYTES (ATTN_SMEM_FLOATS * 4)

__global__ void __launch_bounds__(256) attn_kernel(
    const float* __restrict__ q, const float* __restrict__ k,
    const float* __restrict__ v, const int* __restrict__ mask,
    float* __restrict__ p_out, float* __restrict__ ctx)
{
    extern __shared__ float sm[];
    float* sc = sm;                 // [32][1028]
    float* qs = sc + 32*SCP;        // [32][68]
    float* kv = qs + 32*68;         // [64][68], layout [j][d]
    float* mk = kv + 64*68;         // [1024]

    const int b = blockIdx.z, h = blockIdx.y, i0 = blockIdx.x * 32;
    const int tid = threadIdx.x;
    const int lane = tid & 31, warp = tid >> 5;
    const int r4 = lane >> 2, c4 = lane & 3;
    const int mi_w = warp & 1;
    const int njB  = (warp >> 1) * 2;

    #pragma unroll
    for (int t = 0; t < 2; t++) {
        int idx = tid + t*256;
        int i = idx >> 4, d4 = (idx & 15) * 4;
        float4 qv = *(const float4*)&q[((size_t)(b*S_ + i0 + i))*E_ + h*D_ + d4];
        qv.x *= 0.125f; qv.y *= 0.125f; qv.z *= 0.125f; qv.w *= 0.125f;
        *(float4*)&qs[i*68 + d4] = qv;
    }
    for (int j = tid; j < S_; j += 256) mk[j] = (float)mask[b*S_ + j];
    __syncthreads();

    // phase 1: scores
    for (int jt = 0; jt < 16; jt++) {
        int j0 = jt * 64;
        #pragma unroll
        for (int t = 0; t < 4; t++) {
            int idx = tid + t*256;
            int j = idx >> 4, d4 = (idx & 15) * 4;
            *(float4*)&kv[j*68 + d4] =
                *(const float4*)&k[((size_t)(b*S_ + j0 + j))*E_ + h*D_ + d4];
        }
        __syncthreads();

        float acc[2][4] = {{0,0,0,0},{0,0,0,0}};
        #pragma unroll
        for (int kk = 0; kk < 64; kk += 8) {
            const float* ap = qs + (mi_w*16 + r4)*68 + kk + c4;
            uint32_t a0 = f2tf(ap[0]), a1 = f2tf(ap[8*68]);
            uint32_t a2 = f2tf(ap[4]), a3 = f2tf(ap[8*68 + 4]);
            #pragma unroll
            for (int u = 0; u < 2; u++) {
                const float* bp = kv + ((njB+u)*8 + r4)*68 + kk + c4;
                mma_tf32(acc[u], a0, a1, a2, a3, f2tf(bp[0]), f2tf(bp[4]));
            }
        }
        #pragma unroll
        for (int u = 0; u < 2; u++) {
            int n0 = j0 + (njB+u)*8 + 2*c4;
            int r  = mi_w*16 + r4;
            *(float2*)&sc[r*SCP + n0]     = make_float2(acc[u][0], acc[u][1]);
            *(float2*)&sc[(r+8)*SCP + n0] = make_float2(acc[u][2], acc[u][3]);
        }
        __syncthreads();
    }

    // phase 2: softmax + p write
    for (int r = warp; r < 32; r += 8) {
        float* row = sc + r * SCP;
        float mx = -1e30f;
        for (int j = lane; j < 1024; j += 32) {
            float sv = (mk[j] != 0.f) ? row[j] : -1e9f;
            row[j] = sv;
            mx = fmaxf(mx, sv);
        }
        #pragma unroll
        for (int o = 16; o; o >>= 1) mx = fmaxf(mx, __shfl_xor_sync(0xffffffffu, mx, o));
        float sum = 0.f;
        for (int j = lane; j < 1024; j += 32) {
            float e = __expf(row[j] - mx);
            row[j] = e;
            sum += e;
        }
        #pragma unroll
        for (int o = 16; o; o >>= 1) sum += __shfl_xor_sync(0xffffffffu, sum, o);
        float inv = 1.f / sum;
        float* prow = p_out + (((size_t)(b*H_ + h))*S_ + i0 + r) * S_;
        for (int j = lane; j < 1024; j += 32) {
            float pv = row[j] * inv;
            row[j] = pv;
            prow[j] = pv;
        }
    }
    __syncthreads();

    // phase 3: out = p @ v
    float oacc[2][4] = {{0,0,0,0},{0,0,0,0}};
    for (int jt = 0; jt < 16; jt++) {
        int j0 = jt * 64;
        #pragma unroll
        for (int t = 0; t < 4; t++) {
            int idx = tid + t*256;
            int j = idx >> 4, d4 = (idx & 15) * 4;
            *(float4*)&kv[j*68 + d4] =
                *(const float4*)&v[((size_t)(b*S_ + j0 + j))*E_ + h*D_ + d4];
        }
        __syncthreads();
        #pragma unroll
        for (int kk = 0; kk < 64; kk += 8) {
            const float* ap = sc + (mi_w*16 + r4)*SCP + j0 + kk + c4;
            uint32_t a0 = f2tf(ap[0]), a1 = f2tf(ap[8*SCP]);
            uint32_t a2 = f2tf(ap[4]), a3 = f2tf(ap[8*SCP + 4]);
            #pragma unroll
            for (int u = 0; u < 2; u++) {
                const float* bp = kv + (kk + c4)*68 + (njB+u)*8 + r4;
                mma_tf32(oacc[u], a0, a1, a2, a3, f2tf(bp[0]), f2tf(bp[4*68]));
            }
        }
        __syncthreads();
    }
    {
        int r = mi_w*16 + r4;
        #pragma unroll
        for (int u = 0; u < 2; u++) {
            int c = (njB+u)*8 + 2*c4;
            size_t o0 = ((size_t)(b*S_ + i0 + r))*E_ + h*D_ + c;
            size_t o1 = ((size_t)(b*S_ + i0 + r + 8))*E_ + h*D_ + c;
            *(float2*)&ctx[o0] = make_float2(oacc[u][0], oacc[u][1]);
            *(float2*)&ctx[o1] = make_float2(oacc[u][2], oacc[u][3]);
        }
    }
}

// ---------------------------------------------------------------------------
extern "C" void kernel_launch(void* const* d_in, const int* in_sizes, int n_in,
                              void* d_out, int out_size)
{
    const float* x    = (const float*)d_in[0];
    const int*   mask = (const int*)  d_in[1];
    const float* Wq = (const float*)d_in[2];
    const float* bq = (const float*)d_in[3];
    const float* Wk = (const float*)d_in[4];
    const float* bk = (const float*)d_in[5];
    const float* Wv = (const float*)d_in[6];
    const float* bv = (const float*)d_in[7];
    const float* Wo = (const float*)d_in[8];
    const float* bo = (const float*)d_in[9];
    const float* Wgq = (const float*)d_in[10];
    const float* bgq = (const float*)d_in[11];
    const float* Wgk = (const float*)d_in[12];
    const float* bgk = (const float*)d_in[13];
    const float* qg_wq = (const float*)d_in[14];
    const float* qg_bq = (const float*)d_in[15];
    const float* qg_wk = (const float*)d_in[16];
    const float* qg_bk = (const float*)d_in[17];
    const float* kg_wq = (const float*)d_in[18];
    const float* kg_bq = (const float*)d_in[19];
    const float* kg_wk = (const float*)d_in[20];
    const float* kg_bk = (const float*)d_in[21];

    float* out   = (float*)d_out;
    float* p_out = out + (size_t)S_ * B_ * E_;

    float *qb, *kb, *vb, *ctxb, *gqb, *gkb;
    cudaGetSymbolAddress((void**)&qb,   g_q);
    cudaGetSymbolAddress((void**)&kb,   g_k);
    cudaGetSymbolAddress((void**)&vb,   g_v);
    cudaGetSymbolAddress((void**)&ctxb, g_ctx);
    cudaGetSymbolAddress((void**)&gqb,  g_gq);
    cudaGetSymbolAddress((void**)&gkb,  g_gk);

    cudaFuncSetAttribute(attn_kernel, cudaFuncAttributeMaxDynamicSharedMemorySize,
                         ATTN_SMEM_BYTES);

    msum_kernel<<<1, 128>>>(mask);
    mean_kernel<<<dim3(E_/64, B_), 256>>>(x, mask);

    tgemm<<<dim3(8, 32), 256>>>(x, Wq, bq, qb, 1, 0);
    tgemm<<<dim3(8, 32), 256>>>(x, Wk, bk, kb, 1, 0);
    tgemm<<<dim3(8, 32), 256>>>(x, Wv, bv, vb, 1, 0);

    gproj_kernel<<<512, 256>>>(Wgq, bgq, gqb);
    gproj_kernel<<<512, 256>>>(Wgk, bgk, gkb);

    gate_kernel<<<8192, 256>>>(qb, gqb, qg_wq, qg_bq, qg_wk, qg_bk);
    gate_kernel<<<8192, 256>>>(kb, gkb, kg_wq, kg_bq, kg_wk, kg_bk);

    attn_kernel<<<dim3(S_/32, H_, B_), 256, ATTN_SMEM_BYTES>>>(
        qb, kb, vb, mask, p_out, ctxb);

    tgemm<<<dim3(8, 32), 256>>>(ctxb, Wo, bo, out, 0, 1);
}

// round 4
// speedup vs baseline: 2.8449x; 1.3832x over previous
#include <cuda_runtime.h>
#include <cstdint>

#define B_ 4
#define S_ 1024
#define E_ 1024
#define H_ 16
#define D_ 64

__device__ float g_qkv[3*B_*S_*E_];
__device__ float g_ctx[B_*S_*E_];
__device__ float g_g[B_*E_];
__device__ float g_gq[B_*E_];
__device__ float g_gk[B_*E_];
__device__ float g_minv[B_];

__device__ __forceinline__ uint32_t fbits(float f) { return __float_as_uint(f); }

// round-to-nearest tf32 conversion (returns bit pattern)
__device__ __forceinline__ uint32_t f2tf(float f) {
    uint32_t u;
    asm("cvt.rna.tf32.f32 %0, %1;" : "=r"(u) : "f"(f));
    return u;
}

__device__ __forceinline__ float tfround(float f) {
    return __uint_as_float(f2tf(f));
}

__device__ __forceinline__ void mma_tf32(float c[4],
    uint32_t a0, uint32_t a1, uint32_t a2, uint32_t a3,
    uint32_t b0, uint32_t b1)
{
    asm volatile(
        "mma.sync.aligned.m16n8k8.row.col.f32.tf32.tf32.f32 "
        "{%0,%1,%2,%3}, {%4,%5,%6,%7}, {%8,%9}, {%0,%1,%2,%3};"
        : "+f"(c[0]), "+f"(c[1]), "+f"(c[2]), "+f"(c[3])
        : "r"(a0), "r"(a1), "r"(a2), "r"(a3), "r"(b0), "r"(b1));
}

__device__ __forceinline__ void cp16(uint32_t saddr, const void* g) {
    asm volatile("cp.async.cg.shared.global [%0], [%1], 16;" :: "r"(saddr), "l"(g));
}

// ---------------------------------------------------------------------------
__global__ void msum_kernel(const int* __restrict__ mask) {
    int b = threadIdx.x >> 5, lane = threadIdx.x & 31;
    float s = 0.f;
    for (int j = lane; j < S_; j += 32) s += (float)mask[b*S_ + j];
    #pragma unroll
    for (int o = 16; o; o >>= 1) s += __shfl_xor_sync(0xffffffffu, s, o);
    if (lane == 0) g_minv[b] = 1.0f / fmaxf(s, 1e-9f);
}

__global__ void mean_kernel(const float* __restrict__ x, const int* __restrict__ mask) {
    __shared__ float part[4][64];
    int b  = blockIdx.y;
    int e0 = blockIdx.x * 64;
    int el = threadIdx.x & 63, sq = threadIdx.x >> 6;
    float acc = 0.f;
    int sbeg = sq * 256;
    for (int s = sbeg; s < sbeg + 256; s++) {
        float m = (float)mask[b*S_ + s];
        acc += x[((size_t)s*B_ + b)*E_ + e0 + el] * m;
    }
    part[sq][el] = acc;
    __syncthreads();
    if (threadIdx.x < 64) {
        float t = part[0][el] + part[1][el] + part[2][el] + part[3][el];
        g_g[b*E_ + e0 + el] = t * g_minv[b];
    }
}

// ---------------------------------------------------------------------------
// tf32 GEMM core. Y[t,n] = sum_k A[t,k] W[n,k] + bias[n]
#define GPAD 20
#define GSTG (128*GPAD)

__device__ __forceinline__ void tgemm_body(
    const float* __restrict__ A, const float* __restrict__ W,
    const float* __restrict__ bias, float* __restrict__ Y,
    int permIn, int permOut, int bx, int by,
    float (*As)[GSTG], float (*Bs)[GSTG])
{
    const int tid = threadIdx.x;
    const int lane = tid & 31, warp = tid >> 5;
    const int wm = (warp & 1) * 64, wn = (warp >> 1) * 32;
    const int r4 = lane >> 2, c4 = lane & 3;

    uint32_t aBase = (uint32_t)__cvta_generic_to_shared(&As[0][0]);
    uint32_t bBase = (uint32_t)__cvta_generic_to_shared(&Bs[0][0]);

    int row0 = tid >> 2,         k40 = (tid & 3) * 4;
    int row1 = (tid + 256) >> 2, k41 = ((tid + 256) & 3) * 4;
    int am0 = by*128 + row0;
    int am1 = by*128 + row1;
    int ar0 = permIn ? ((am0 & 1023)*B_ + (am0 >> 10)) : am0;
    int ar1 = permIn ? ((am1 & 1023)*B_ + (am1 >> 10)) : am1;
    const float* ap0 = A + (size_t)ar0*1024 + k40;
    const float* ap1 = A + (size_t)ar1*1024 + k41;
    const float* wp0 = W + ((size_t)(bx*128 + row0))*1024 + k40;
    const float* wp1 = W + ((size_t)(bx*128 + row1))*1024 + k41;
    uint32_t ad0 = aBase + (row0*GPAD + k40)*4, ad1 = aBase + (row1*GPAD + k41)*4;
    uint32_t bd0 = bBase + (row0*GPAD + k40)*4, bd1 = bBase + (row1*GPAD + k41)*4;

    auto loadStage = [&](int stg, int k0) {
        uint32_t so = stg * GSTG * 4;
        cp16(ad0 + so, ap0 + k0);
        cp16(ad1 + so, ap1 + k0);
        cp16(bd0 + so, wp0 + k0);
        cp16(bd1 + so, wp1 + k0);
        asm volatile("cp.async.commit_group;" ::: "memory");
    };

    float acc[4][4][4];
    #pragma unroll
    for (int mi = 0; mi < 4; mi++)
        #pragma unroll
        for (int nj = 0; nj < 4; nj++)
            #pragma unroll
            for (int t = 0; t < 4; t++) acc[mi][nj][t] = 0.f;

    loadStage(0, 0);
    for (int ks = 0; ks < 64; ks++) {
        if (ks < 63) {
            loadStage((ks + 1) & 1, (ks + 1) * 16);
            asm volatile("cp.async.wait_group 1;" ::: "memory");
        } else {
            asm volatile("cp.async.wait_group 0;" ::: "memory");
        }
        __syncthreads();
        const float* as = As[ks & 1];
        const float* bs = Bs[ks & 1];
        #pragma unroll
        for (int kk = 0; kk < 16; kk += 8) {
            uint32_t af[4][4];
            #pragma unroll
            for (int mi = 0; mi < 4; mi++) {
                const float* ap = as + (wm + mi*16 + r4)*GPAD + kk + c4;
                af[mi][0] = f2tf(ap[0]);
                af[mi][1] = f2tf(ap[8*GPAD]);
                af[mi][2] = f2tf(ap[4]);
                af[mi][3] = f2tf(ap[8*GPAD + 4]);
            }
            #pragma unroll
            for (int nj = 0; nj < 4; nj++) {
                const float* bp = bs + (wn + nj*8 + r4)*GPAD + kk + c4;
                uint32_t b0 = f2tf(bp[0]), b1 = f2tf(bp[4]);
                #pragma unroll
                for (int mi = 0; mi < 4; mi++)
                    mma_tf32(acc[mi][nj], af[mi][0], af[mi][1], af[mi][2], af[mi][3], b0, b1);
            }
        }
        __syncthreads();
    }

    #pragma unroll
    for (int mi = 0; mi < 4; mi++) {
        #pragma unroll
        for (int r2 = 0; r2 < 2; r2++) {
            int m = by*128 + wm + mi*16 + r4 + r2*8;
            int orow = permOut ? ((m & 1023)*B_ + (m >> 10)) : m;
            float* yp = Y + (size_t)orow*1024 + bx*128 + wn;
            const float* bi = bias + bx*128 + wn;
            #pragma unroll
            for (int nj = 0; nj < 4; nj++) {
                int c = nj*8 + 2*c4;
                float2 val;
                val.x = acc[mi][nj][r2*2 + 0] + bi[c];
                val.y = acc[mi][nj][r2*2 + 1] + bi[c + 1];
                *(float2*)(yp + c) = val;
            }
        }
    }
}

__global__ void __launch_bounds__(256) tgemm_qkv(
    const float* __restrict__ A,
    const float* __restrict__ Wq, const float* __restrict__ bq,
    const float* __restrict__ Wk, const float* __restrict__ bk,
    const float* __restrict__ Wv, const float* __restrict__ bv,
    float* __restrict__ Y)
{
    __shared__ float As[2][GSTG];
    __shared__ float Bs[2][GSTG];
    int sel = blockIdx.z;
    const float* W = (sel == 0) ? Wq : (sel == 1) ? Wk : Wv;
    const float* bi = (sel == 0) ? bq : (sel == 1) ? bk : bv;
    tgemm_body(A, W, bi, Y + (size_t)sel*B_*S_*E_, 1, 0, blockIdx.x, blockIdx.y, As, Bs);
}

__global__ void __launch_bounds__(256) tgemm_wo(
    const float* __restrict__ A, const float* __restrict__ W,
    const float* __restrict__ bias, float* __restrict__ Y)
{
    __shared__ float As[2][GSTG];
    __shared__ float Bs[2][GSTG];
    tgemm_body(A, W, bias, Y, 0, 1, blockIdx.x, blockIdx.y, As, Bs);
}

// ---------------------------------------------------------------------------
__global__ void gproj_kernel(const float* __restrict__ Wg, const float* __restrict__ bg,
                             float* __restrict__ out)
{
    int gw = (blockIdx.x * blockDim.x + threadIdx.x) >> 5;
    int lane = threadIdx.x & 31;
    int b = gw >> 10, o = gw & 1023;
    float acc = 0.f;
    #pragma unroll
    for (int e = lane * 4; e < E_; e += 128) {
        float4 gv = *(const float4*)&g_g[b*E_ + e];
        float4 wv = *(const float4*)&Wg[(size_t)o*E_ + e];
        acc += gv.x*wv.x + gv.y*wv.y + gv.z*wv.z + gv.w*wv.w;
    }
    #pragma unroll
    for (int of = 16; of; of >>= 1) acc += __shfl_xor_sync(0xffffffffu, acc, of);
    if (lane == 0) out[b*E_ + o] = acc + bg[o];
}

__global__ void gate_kernel(float* __restrict__ buf, const float* __restrict__ gbuf,
                            const float* __restrict__ wv, const float* __restrict__ bvp,
                            const float* __restrict__ wg, const float* __restrict__ bgp)
{
    int gw   = (blockIdx.x * blockDim.x + threadIdx.x) >> 5;
    int lane = threadIdx.x & 31;
    int b = gw >> 14, h = (gw >> 10) & 15, s = gw & 1023;
    size_t off = ((size_t)(b*S_ + s))*E_ + h*D_;
    int goff = b*E_ + h*D_;
    float q0 = buf[off + lane],        q1 = buf[off + 32 + lane];
    float g0 = gbuf[goff + lane],      g1 = gbuf[goff + 32 + lane];
    float part = q0*wv[lane] + q1*wv[32 + lane] + g0*wg[lane] + g1*wg[32 + lane];
    #pragma unroll
    for (int o = 16; o; o >>= 1) part += __shfl_xor_sync(0xffffffffu, part, o);
    float alpha = 1.f / (1.f + __expf(-(part + bvp[0] + bgp[0])));
    buf[off + lane]      = q0 + alpha * (g0 - q0);
    buf[off + 32 + lane] = q1 + alpha * (g1 - q1);
}

// ---------------------------------------------------------------------------
// fused attention, cp.async double-buffered K/V chunks.
// A-operands (qs, sc) are pre-rounded to tf32 at smem-store time -> raw-bit loads.
// B-operands (kv chunks) use cvt.rna at fragment load.
#define SCP 1028
#define KVW 68
#define ATTN_SMEM_FLOATS (32*SCP + 32*KVW + 2*64*KVW + 1024)
#define ATTN_SMEM_BYTES (ATTN_SMEM_FLOATS * 4)

__global__ void __launch_bounds__(256) attn_kernel(
    const float* __restrict__ q, const float* __restrict__ k,
    const float* __restrict__ v, const int* __restrict__ mask,
    float* __restrict__ p_out, float* __restrict__ ctx)
{
    extern __shared__ float sm[];
    float* sc  = sm;                    // [32][1028]
    float* qs  = sc + 32*SCP;           // [32][68] scaled q (tf32-rounded)
    float* kvs = qs + 32*KVW;           // [2][64][68] K/V double buffer
    float* mk  = kvs + 2*64*KVW;        // [1024]

    const int b = blockIdx.z, h = blockIdx.y, i0 = blockIdx.x * 32;
    const int tid = threadIdx.x;
    const int lane = tid & 31, warp = tid >> 5;
    const int r4 = lane >> 2, c4 = lane & 3;
    const int mi_w = warp & 1;
    const int njB  = (warp >> 1) * 2;

    uint32_t kvBase = (uint32_t)__cvta_generic_to_shared(kvs);

    // chunk c: 0..15 = K chunks, 16..31 = V chunks
    auto issue_chunk = [&](int c) {
        const float* src = (c < 16) ? k : v;
        int j0 = (c & 15) * 64;
        uint32_t so = (uint32_t)((c & 1) * 64 * KVW * 4);
        #pragma unroll
        for (int t = 0; t < 4; t++) {
            int idx = tid + t*256;
            int j = idx >> 4, d4 = (idx & 15) * 4;
            cp16(kvBase + so + (j*KVW + d4)*4,
                 src + ((size_t)(b*S_ + j0 + j))*E_ + h*D_ + d4);
        }
        asm volatile("cp.async.commit_group;" ::: "memory");
    };

    issue_chunk(0);

    #pragma unroll
    for (int t = 0; t < 2; t++) {
        int idx = tid + t*256;
        int i = idx >> 4, d4 = (idx & 15) * 4;
        float4 qv = *(const float4*)&q[((size_t)(b*S_ + i0 + i))*E_ + h*D_ + d4];
        qv.x = tfround(qv.x * 0.125f); qv.y = tfround(qv.y * 0.125f);
        qv.z = tfround(qv.z * 0.125f); qv.w = tfround(qv.w * 0.125f);
        *(float4*)&qs[i*KVW + d4] = qv;
    }
    for (int j = tid; j < S_; j += 256) mk[j] = (float)mask[b*S_ + j];

    // ---- phase 1: scores = q @ k^T ----
    for (int jt = 0; jt < 16; jt++) {
        issue_chunk(jt + 1);   // jt==15 prefetches V chunk 0
        asm volatile("cp.async.wait_group 1;" ::: "memory");
        __syncthreads();
        const float* kc = kvs + (jt & 1) * 64 * KVW;

        float acc[2][4] = {{0,0,0,0},{0,0,0,0}};
        #pragma unroll
        for (int kk = 0; kk < 64; kk += 8) {
            const float* ap = qs + (mi_w*16 + r4)*KVW + kk + c4;
            uint32_t a0 = fbits(ap[0]), a1 = fbits(ap[8*KVW]);
            uint32_t a2 = fbits(ap[4]), a3 = fbits(ap[8*KVW + 4]);
            #pragma unroll
            for (int u = 0; u < 2; u++) {
                const float* bp = kc + ((njB+u)*8 + r4)*KVW + kk + c4;
                mma_tf32(acc[u], a0, a1, a2, a3, f2tf(bp[0]), f2tf(bp[4]));
            }
        }
        int j0 = jt * 64;
        #pragma unroll
        for (int u = 0; u < 2; u++) {
            int n0 = j0 + (njB+u)*8 + 2*c4;
            int r  = mi_w*16 + r4;
            *(float2*)&sc[r*SCP + n0]     = make_float2(acc[u][0], acc[u][1]);
            *(float2*)&sc[(r+8)*SCP + n0] = make_float2(acc[u][2], acc[u][3]);
        }
        __syncthreads();
    }

    // ---- phase 2: softmax + p write (V chunk 0 in flight) ----
    for (int r = warp; r < 32; r += 8) {
        float* row = sc + r * SCP;
        float mx = -1e30f;
        for (int j = lane; j < 1024; j += 32) {
            float sv = (mk[j] != 0.f) ? row[j] : -1e9f;
            row[j] = sv;
            mx = fmaxf(mx, sv);
        }
        #pragma unroll
        for (int o = 16; o; o >>= 1) mx = fmaxf(mx, __shfl_xor_sync(0xffffffffu, mx, o));
        float sum = 0.f;
        for (int j = lane; j < 1024; j += 32) {
            float e = __expf(row[j] - mx);
            row[j] = e;
            sum += e;
        }
        #pragma unroll
        for (int o = 16; o; o >>= 1) sum += __shfl_xor_sync(0xffffffffu, sum, o);
        float inv = 1.f / sum;
        float* prow = p_out + (((size_t)(b*H_ + h))*S_ + i0 + r) * S_;
        for (int j = lane; j < 1024; j += 32) {
            float pv = row[j] * inv;
            prow[j] = pv;              // full fp32 p_attn output
            row[j] = tfround(pv);      // tf32-rounded for phase-3 A operand
        }
    }

    // ---- phase 3: out = p @ v ----
    float oacc[2][4] = {{0,0,0,0},{0,0,0,0}};
    for (int c = 16; c < 32; c++) {
        if (c < 31) {
            issue_chunk(c + 1);
            asm volatile("cp.async.wait_group 1;" ::: "memory");
        } else {
            asm volatile("cp.async.wait_group 0;" ::: "memory");
        }
        __syncthreads();
        const float* vc = kvs + (c & 1) * 64 * KVW;
        int j0 = (c - 16) * 64;
        #pragma unroll
        for (int kk = 0; kk < 64; kk += 8) {
            const float* ap = sc + (mi_w*16 + r4)*SCP + j0 + kk + c4;
            uint32_t a0 = fbits(ap[0]), a1 = fbits(ap[8*SCP]);
            uint32_t a2 = fbits(ap[4]), a3 = fbits(ap[8*SCP + 4]);
            #pragma unroll
            for (int u = 0; u < 2; u++) {
                const float* bp = vc + (kk + c4)*KVW + (njB+u)*8 + r4;
                mma_tf32(oacc[u], a0, a1, a2, a3, f2tf(bp[0]), f2tf(bp[4*KVW]));
            }
        }
        __syncthreads();
    }
    {
        int r = mi_w*16 + r4;
        #pragma unroll
        for (int u = 0; u < 2; u++) {
            int cc = (njB+u)*8 + 2*c4;
            size_t o0 = ((size_t)(b*S_ + i0 + r))*E_ + h*D_ + cc;
            size_t o1 = ((size_t)(b*S_ + i0 + r + 8))*E_ + h*D_ + cc;
            *(float2*)&ctx[o0] = make_float2(oacc[u][0], oacc[u][1]);
            *(float2*)&ctx[o1] = make_float2(oacc[u][2], oacc[u][3]);
        }
    }
}

// ---------------------------------------------------------------------------
extern "C" void kernel_launch(void* const* d_in, const int* in_sizes, int n_in,
                              void* d_out, int out_size)
{
    const float* x    = (const float*)d_in[0];
    const int*   mask = (const int*)  d_in[1];
    const float* Wq = (const float*)d_in[2];
    const float* bq = (const float*)d_in[3];
    const float* Wk = (const float*)d_in[4];
    const float* bk = (const float*)d_in[5];
    const float* Wv = (const float*)d_in[6];
    const float* bv = (const float*)d_in[7];
    const float* Wo = (const float*)d_in[8];
    const float* bo = (const float*)d_in[9];
    const float* Wgq = (const float*)d_in[10];
    const float* bgq = (const float*)d_in[11];
    const float* Wgk = (const float*)d_in[12];
    const float* bgk = (const float*)d_in[13];
    const float* qg_wq = (const float*)d_in[14];
    const float* qg_bq = (const float*)d_in[15];
    const float* qg_wk = (const float*)d_in[16];
    const float* qg_bk = (const float*)d_in[17];
    const float* kg_wq = (const float*)d_in[18];
    const float* kg_bq = (const float*)d_in[19];
    const float* kg_wk = (const float*)d_in[20];
    const float* kg_bk = (const float*)d_in[21];

    float* out   = (float*)d_out;
    float* p_out = out + (size_t)S_ * B_ * E_;

    float *qkvb, *ctxb, *gqb, *gkb;
    cudaGetSymbolAddress((void**)&qkvb, g_qkv);
    cudaGetSymbolAddress((void**)&ctxb, g_ctx);
    cudaGetSymbolAddress((void**)&gqb,  g_gq);
    cudaGetSymbolAddress((void**)&gkb,  g_gk);
    float* qb = qkvb;
    float* kb = qkvb + (size_t)B_*S_*E_;
    float* vb = qkvb + 2*(size_t)B_*S_*E_;

    cudaFuncSetAttribute(attn_kernel, cudaFuncAttributeMaxDynamicSharedMemorySize,
                         ATTN_SMEM_BYTES);

    msum_kernel<<<1, 128>>>(mask);
    mean_kernel<<<dim3(E_/64, B_), 256>>>(x, mask);

    tgemm_qkv<<<dim3(8, 32, 3), 256>>>(x, Wq, bq, Wk, bk, Wv, bv, qkvb);

    gproj_kernel<<<512, 256>>>(Wgq, bgq, gqb);
    gproj_kernel<<<512, 256>>>(Wgk, bgk, gkb);

    gate_kernel<<<8192, 256>>>(qb, gqb, qg_wq, qg_bq, qg_wk, qg_bk);
    gate_kernel<<<8192, 256>>>(kb, gkb, kg_wq, kg_bq, kg_wk, kg_bk);

    attn_kernel<<<dim3(S_/32, H_, B_), 256, ATTN_SMEM_BYTES>>>(
        qb, kb, vb, mask, p_out, ctxb);

    tgemm_wo<<<dim3(8, 32), 256>>>(ctxb, Wo, bo, out);
}